// round 1
// baseline (speedup 1.0000x reference)
#include <cuda_runtime.h>
#include <math.h>

#define NNODES 40000
#define NEDGES 400000
#define ETOT   (NEDGES + NNODES)
#define NHEADS 32
#define NGRAPH 256
#define NCOND  100
#define BN_EPS 1e-5f

// ---------------- scratch (static device allocations only) ----------------
__device__ float    g_h[115200000];          // [N, 32*90] max  (460.8MB)
__device__ float    g_act[NNODES * 90];      // layer activations
__device__ float    g_out[NNODES * 90];      // GAT output accumulator
__device__ float    g_ssrc[NNODES * NHEADS];
__device__ float    g_sdst[NNODES * NHEADS];
__device__ unsigned g_m[NNODES * NHEADS];    // ordered-uint encoded max
__device__ float    g_denom[NNODES * NHEADS];
__device__ float    g_Wp[128 * 2880];        // BN-scaled weights
__device__ float    g_rb[2880];              // row bias = shift @ W
__device__ float    g_bnsum[2 * 128];        // per-col sum / sumsq
__device__ float    g_scale[128];
__device__ float    g_shift[128];
__device__ float    g_pool[NGRAPH * 5];
__device__ float    g_cnt[NGRAPH];

// ---------------- helpers ----------------
__device__ __forceinline__ unsigned enc_f(float f) {
    unsigned u = __float_as_uint(f);
    return (u & 0x80000000u) ? ~u : (u | 0x80000000u);
}
__device__ __forceinline__ float dec_f(unsigned e) {
    return (e & 0x80000000u) ? __uint_as_float(e ^ 0x80000000u)
                             : __uint_as_float(~e);
}
__device__ __forceinline__ float leaky(float v, float s) { return v > 0.f ? v : s * v; }

// ---------------- BatchNorm folding ----------------
// per-column partial sums (blocks over row chunks, thread = column)
__global__ void bn_accum(const float* __restrict__ X, int n, int ci, float* sums) {
    int col = threadIdx.x;
    if (col >= ci) return;
    int r0 = blockIdx.x * 256;
    int r1 = r0 + 256; if (r1 > n) r1 = n;
    float s = 0.f, s2 = 0.f;
    for (int r = r0; r < r1; r++) {
        float v = X[r * ci + col];
        s += v; s2 += v * v;
    }
    atomicAdd(&sums[col], s);
    atomicAdd(&sums[ci + col], s2);
}

__global__ void bn_final(const float* sums, const float* __restrict__ g,
                         const float* __restrict__ be, float* scale, float* shift,
                         int n, int ci) {
    int c = blockIdx.x * blockDim.x + threadIdx.x;
    if (c >= ci) return;
    float mu  = sums[c] / (float)n;
    float var = sums[ci + c] / (float)n - mu * mu;
    float rs  = rsqrtf(var + BN_EPS);
    float sc  = g[c] * rs;
    scale[c] = sc;
    shift[c] = be[c] - mu * sc;
}

__global__ void prep_w(const float* __restrict__ W, const float* __restrict__ scale,
                       float* Wp, int ci, int hco) {
    int i = blockIdx.x * blockDim.x + threadIdx.x;
    if (i >= ci * hco) return;
    Wp[i] = W[i] * scale[i / hco];
}

__global__ void rowbias_k(const float* __restrict__ W, const float* __restrict__ shift,
                          float* rb, int ci, int hco) {
    int j = blockIdx.x * blockDim.x + threadIdx.x;
    if (j >= hco) return;
    float s = 0.f;
    for (int c = 0; c < ci; c++) s += shift[c] * W[c * hco + j];
    rb[j] = s;
}

// ---------------- SGEMM: C[M,Nn] = A[M,K] @ B[K,Nn] + bias[col] ----------------
__global__ __launch_bounds__(256)
void sgemm_bias(const float* __restrict__ A, const float* __restrict__ B,
                const float* __restrict__ bias, float* __restrict__ C,
                int M, int Nn, int K) {
    __shared__ float As[8][128];
    __shared__ float Bs[8][128];
    int tid = threadIdx.x;
    int bm = blockIdx.y * 128;
    int bn = blockIdx.x * 128;
    int tx = tid & 15, ty = tid >> 4;
    float acc[8][8];
#pragma unroll
    for (int i = 0; i < 8; i++)
#pragma unroll
        for (int j = 0; j < 8; j++) acc[i][j] = 0.f;

    for (int k0 = 0; k0 < K; k0 += 8) {
#pragma unroll
        for (int it = 0; it < 4; it++) {
            int e = tid + it * 256;
            int m = e >> 3, kk = e & 7;
            int gm = bm + m, gk = k0 + kk;
            float v = 0.f;
            if (gm < M && gk < K) v = A[gm * K + gk];
            As[kk][m] = v;
        }
#pragma unroll
        for (int it = 0; it < 4; it++) {
            int e = tid + it * 256;
            int kk = e >> 7, n = e & 127;
            int gn = bn + n, gk = k0 + kk;
            float v = 0.f;
            if (gk < K && gn < Nn) v = B[gk * Nn + gn];
            Bs[kk][n] = v;
        }
        __syncthreads();
#pragma unroll
        for (int kk = 0; kk < 8; kk++) {
            float ar[8], br[8];
#pragma unroll
            for (int i = 0; i < 8; i++) ar[i] = As[kk][ty * 8 + i];
#pragma unroll
            for (int j = 0; j < 8; j++) br[j] = Bs[kk][tx * 8 + j];
#pragma unroll
            for (int i = 0; i < 8; i++)
#pragma unroll
                for (int j = 0; j < 8; j++) acc[i][j] += ar[i] * br[j];
        }
        __syncthreads();
    }
#pragma unroll
    for (int i = 0; i < 8; i++) {
        int gm = bm + ty * 8 + i;
        if (gm >= M) continue;
#pragma unroll
        for (int j = 0; j < 8; j++) {
            int gn = bn + tx * 8 + j;
            if (gn < Nn) C[gm * Nn + gn] = acc[i][j] + bias[gn];
        }
    }
}

// ---------------- attention scores: warp per (node, head) row ----------------
__global__ void attn_scores(const float* __restrict__ h, const float* __restrict__ as_,
                            const float* __restrict__ ad_, float* ssrc, float* sdst,
                            int n, int co) {
    int w = (blockIdx.x * blockDim.x + threadIdx.x) >> 5;
    int lane = threadIdx.x & 31;
    if (w >= n * NHEADS) return;
    int hh = w & 31;
    const float* hr = h + (size_t)w * co;
    float s1 = 0.f, s2 = 0.f;
    for (int c = lane; c < co; c += 32) {
        float v = hr[c];
        s1 += v * as_[hh * co + c];
        s2 += v * ad_[hh * co + c];
    }
#pragma unroll
    for (int o = 16; o; o >>= 1) {
        s1 += __shfl_xor_sync(0xffffffffu, s1, o);
        s2 += __shfl_xor_sync(0xffffffffu, s2, o);
    }
    if (lane == 0) { ssrc[w] = s1; sdst[w] = s2; }
}

// ---------------- edge pass 1: segment max ----------------
__global__ void edge_max(const int* __restrict__ ei, const float* __restrict__ ssrc,
                         const float* __restrict__ sdst, unsigned* m) {
    int idx = blockIdx.x * blockDim.x + threadIdx.x;
    if (idx >= ETOT * NHEADS) return;
    int hh = idx & 31, e = idx >> 5;
    int s, d;
    if (e < NEDGES) { s = ei[e]; d = ei[NEDGES + e]; }
    else            { s = d = e - NEDGES; }
    float l = leaky(ssrc[s * 32 + hh] + sdst[d * 32 + hh], 0.2f);
    atomicMax(&m[d * 32 + hh], enc_f(l));
}

// ---------------- edge pass 2: exp-sum ----------------
__global__ void edge_expsum(const int* __restrict__ ei, const float* __restrict__ ssrc,
                            const float* __restrict__ sdst, const unsigned* __restrict__ m,
                            float* denom) {
    int idx = blockIdx.x * blockDim.x + threadIdx.x;
    if (idx >= ETOT * NHEADS) return;
    int hh = idx & 31, e = idx >> 5;
    int s, d;
    if (e < NEDGES) { s = ei[e]; d = ei[NEDGES + e]; }
    else            { s = d = e - NEDGES; }
    float l = leaky(ssrc[s * 32 + hh] + sdst[d * 32 + hh], 0.2f);
    float mv = dec_f(m[d * 32 + hh]);
    atomicAdd(&denom[d * 32 + hh], expf(l - mv));
}

// ---------------- edge pass 3: weighted aggregation (warp per edge) ----------------
__global__ void edge_agg(const int* __restrict__ ei, const float* __restrict__ h,
                         const float* __restrict__ ssrc, const float* __restrict__ sdst,
                         const unsigned* __restrict__ m, const float* __restrict__ denom,
                         float* out, int co) {
    int w = (blockIdx.x * blockDim.x + threadIdx.x) >> 5;
    int lane = threadIdx.x & 31;
    if (w >= ETOT) return;
    int s, d;
    if (w < NEDGES) { s = ei[w]; d = ei[NEDGES + w]; }
    else            { s = d = w - NEDGES; }
    // lane = head: compute this head's alpha
    float l = leaky(ssrc[s * 32 + lane] + sdst[d * 32 + lane], 0.2f);
    float mv = dec_f(m[d * 32 + lane]);
    float alpha = expf(l - mv) / denom[d * 32 + lane];

    const float* hb = h + (size_t)(s * NHEADS) * co;
    for (int c0 = 0; c0 < co; c0 += 32) {
        int c = c0 + lane;
        bool ok = (c < co);
        float acc = 0.f;
#pragma unroll 8
        for (int hh = 0; hh < NHEADS; hh++) {
            float a = __shfl_sync(0xffffffffu, alpha, hh);
            float v = ok ? hb[hh * co + c] : 0.f;
            acc += a * v;
        }
        if (ok) atomicAdd(&out[d * co + c], acc);
    }
}

// ---------------- finalize: out/H + bias, leaky(0.01) ----------------
__global__ void finalize_k(const float* __restrict__ out, const float* __restrict__ b,
                           float* act, int n, int co) {
    int idx = blockIdx.x * blockDim.x + threadIdx.x;
    if (idx >= n * co) return;
    float v = out[idx] * (1.0f / 32.0f) + b[idx % co];
    act[idx] = leaky(v, 0.01f);
}

// ---------------- pooling + head ----------------
__global__ void pool_k(const float* __restrict__ act, const int* __restrict__ batch,
                       float* pool, float* cnt) {
    int nn = blockIdx.x * blockDim.x + threadIdx.x;
    if (nn >= NNODES) return;
    int gi = batch[nn];
    atomicAdd(&cnt[gi], 1.0f);
#pragma unroll
    for (int c = 0; c < 5; c++) atomicAdd(&pool[gi * 5 + c], act[nn * 5 + c]);
}

__global__ void head_k(const float* __restrict__ pool, const float* __restrict__ cnt,
                       const float* __restrict__ cond, const float* __restrict__ fcW,
                       const float* __restrict__ fcb, float* out) {
    int gi = blockIdx.x * blockDim.x + threadIdx.x;
    if (gi >= NGRAPH) return;
    float cd = 0.f;
    for (int k = 0; k < NCOND; k++) cd += cond[k] * fcW[5 + k];
    float c = fmaxf(cnt[gi], 1.0f);
    float acc = fcb[0] + cd;
#pragma unroll
    for (int j = 0; j < 5; j++) acc += (pool[gi * 5 + j] / c) * fcW[j];
    out[gi] = 1.0f / (1.0f + expf(-acc));
}

// ---------------- host orchestration ----------------
extern "C" void kernel_launch(void* const* d_in, const int* in_sizes, int n_in,
                              void* d_out, int out_size) {
    (void)in_sizes; (void)n_in;
    const float* x     = (const float*)d_in[0];
    const int*   ei    = (const int*)d_in[1];
    const int*   batch = (const int*)d_in[2];
    const float* cond  = (const float*)d_in[3];
    const float* W[4]  = {(const float*)d_in[4],  (const float*)d_in[8],
                          (const float*)d_in[12], (const float*)d_in[16]};
    const float* As[4] = {(const float*)d_in[5],  (const float*)d_in[9],
                          (const float*)d_in[13], (const float*)d_in[17]};
    const float* Ad[4] = {(const float*)d_in[6],  (const float*)d_in[10],
                          (const float*)d_in[14], (const float*)d_in[18]};
    const float* Bb[4] = {(const float*)d_in[7],  (const float*)d_in[11],
                          (const float*)d_in[15], (const float*)d_in[19]};
    const float* G[4]  = {(const float*)d_in[20], (const float*)d_in[22],
                          (const float*)d_in[24], (const float*)d_in[26]};
    const float* Be[4] = {(const float*)d_in[21], (const float*)d_in[23],
                          (const float*)d_in[25], (const float*)d_in[27]};
    const float* fcW = (const float*)d_in[30];
    const float* fcb = (const float*)d_in[31];
    float* outp = (float*)d_out;
    (void)out_size;

    float *p_h, *p_act, *p_out, *p_ssrc, *p_sdst, *p_denom, *p_Wp, *p_rb;
    float *p_bnsum, *p_scale, *p_shift, *p_pool, *p_cnt;
    unsigned* p_m;
    cudaGetSymbolAddress((void**)&p_h, g_h);
    cudaGetSymbolAddress((void**)&p_act, g_act);
    cudaGetSymbolAddress((void**)&p_out, g_out);
    cudaGetSymbolAddress((void**)&p_ssrc, g_ssrc);
    cudaGetSymbolAddress((void**)&p_sdst, g_sdst);
    cudaGetSymbolAddress((void**)&p_m, g_m);
    cudaGetSymbolAddress((void**)&p_denom, g_denom);
    cudaGetSymbolAddress((void**)&p_Wp, g_Wp);
    cudaGetSymbolAddress((void**)&p_rb, g_rb);
    cudaGetSymbolAddress((void**)&p_bnsum, g_bnsum);
    cudaGetSymbolAddress((void**)&p_scale, g_scale);
    cudaGetSymbolAddress((void**)&p_shift, g_shift);
    cudaGetSymbolAddress((void**)&p_pool, g_pool);
    cudaGetSymbolAddress((void**)&p_cnt, g_cnt);

    const int ci_arr[4] = {128, 90, 45, 15};
    const int co_arr[4] = {90, 45, 15, 5};

    const float* X = x;
    const int N = NNODES;
    const int edge_threads = ETOT * NHEADS;

    for (int l = 0; l < 4; l++) {
        int ci = ci_arr[l], co = co_arr[l], hco = NHEADS * co;

        // BatchNorm stats -> fold into (scale, shift)
        cudaMemsetAsync(p_bnsum, 0, 2 * ci * sizeof(float), 0);
        {
            int bdim = ((ci + 31) / 32) * 32;
            bn_accum<<<(N + 255) / 256, bdim>>>(X, N, ci, p_bnsum);
        }
        bn_final<<<1, 128>>>(p_bnsum, G[l], Be[l], p_scale, p_shift, N, ci);
        prep_w<<<(ci * hco + 255) / 256, 256>>>(W[l], p_scale, p_Wp, ci, hco);
        rowbias_k<<<(hco + 255) / 256, 256>>>(W[l], p_shift, p_rb, ci, hco);

        // h = X @ Wp + rb   (BN folded)
        {
            dim3 grid((hco + 127) / 128, (N + 127) / 128);
            sgemm_bias<<<grid, 256>>>(X, p_Wp, p_rb, p_h, N, hco, ci);
        }

        // attention scores
        attn_scores<<<(N * NHEADS * 32 + 255) / 256, 256>>>(p_h, As[l], Ad[l],
                                                            p_ssrc, p_sdst, N, co);

        // softmax over incoming edges per (dst, head)
        cudaMemsetAsync(p_m, 0, N * NHEADS * sizeof(unsigned), 0);
        cudaMemsetAsync(p_denom, 0, N * NHEADS * sizeof(float), 0);
        edge_max<<<(edge_threads + 255) / 256, 256>>>(ei, p_ssrc, p_sdst, p_m);
        edge_expsum<<<(edge_threads + 255) / 256, 256>>>(ei, p_ssrc, p_sdst, p_m, p_denom);

        // weighted aggregation
        cudaMemsetAsync(p_out, 0, N * co * sizeof(float), 0);
        edge_agg<<<(edge_threads + 255) / 256, 256>>>(ei, p_h, p_ssrc, p_sdst,
                                                      p_m, p_denom, p_out, co);
        finalize_k<<<(N * co + 255) / 256, 256>>>(p_out, Bb[l], p_act, N, co);

        X = p_act;
    }

    // global mean pool + FC + sigmoid
    cudaMemsetAsync(p_pool, 0, NGRAPH * 5 * sizeof(float), 0);
    cudaMemsetAsync(p_cnt, 0, NGRAPH * sizeof(float), 0);
    pool_k<<<(NNODES + 255) / 256, 256>>>(p_act, batch, p_pool, p_cnt);
    head_k<<<1, 256>>>(p_pool, p_cnt, cond, fcW, fcb, outp);
}

// round 2
// speedup vs baseline: 1.3884x; 1.3884x over previous
#include <cuda_runtime.h>
#include <math.h>

#define NNODES 40000
#define NEDGES 400000
#define ETOT   (NEDGES + NNODES)
#define NHEADS 32
#define NGRAPH 256
#define NCOND  100
#define BN_EPS 1e-5f

// ---------------- scratch ----------------
__device__ float g_Y[163840000];          // [N, 32*128] max (655MB)
__device__ float g_act[NNODES * 90];
__device__ float g_S[NNODES * 64];        // [N,64]: cols 0..31 = s_src, 32..63 = s_dst
__device__ float g_U[128 * 64];
__device__ float g_P[128 * 64];
__device__ float g_cbias[64];
__device__ float g_V[4096 * 96];          // [K, TNpad]
__device__ float g_obias[96];
__device__ float g_bnsum[2 * 128];
__device__ float g_scale[128];
__device__ float g_shift[128];
__device__ int   g_deg[40960];
__device__ int   g_cursor[40960];
__device__ int   g_rowstart[NNODES + 1];
__device__ int   g_csrc[ETOT];
__device__ float g_pool[NGRAPH * 5];
__device__ float g_cnt[NGRAPH];

__device__ __forceinline__ float leaky(float v, float s) { return v > 0.f ? v : s * v; }

// ================= BatchNorm stats =================
__global__ void bn_accum(const float* __restrict__ X, int n, int ci, float* sums) {
    int col = threadIdx.x;
    if (col >= ci) return;
    int r0 = blockIdx.x * 256;
    int r1 = r0 + 256; if (r1 > n) r1 = n;
    float s = 0.f, s2 = 0.f;
    for (int r = r0; r < r1; r++) {
        float v = X[r * ci + col];
        s += v; s2 += v * v;
    }
    atomicAdd(&sums[col], s);
    atomicAdd(&sums[ci + col], s2);
}

__global__ void bn_final(const float* sums, const float* __restrict__ g,
                         const float* __restrict__ be, float* scale, float* shift,
                         int n, int ci) {
    int c = blockIdx.x * blockDim.x + threadIdx.x;
    if (c >= ci) return;
    float mu  = sums[c] / (float)n;
    float var = sums[ci + c] / (float)n - mu * mu;
    float rs  = rsqrtf(var + BN_EPS);
    float sc  = g[c] * rs;
    scale[c] = sc;
    shift[c] = be[c] - mu * sc;
}

// ================= parameter preprocessing =================
// U[c,u] = sum_j W[c, h*co+j] * a[h,j]   (u<32: a_src, else a_dst)
// P[c,u] = scale[c] * U[c,u]
__global__ void p_build(const float* __restrict__ W, const float* __restrict__ as_,
                        const float* __restrict__ ad_, const float* __restrict__ scale,
                        float* U, float* P, int ci, int co, int hco) {
    int idx = blockIdx.x * blockDim.x + threadIdx.x;
    if (idx >= ci * 64) return;
    int c = idx >> 6, u = idx & 63;
    int h = u & 31;
    const float* a = (u < 32) ? as_ : ad_;
    float s = 0.f;
    for (int j = 0; j < co; j++) s += W[c * hco + h * co + j] * a[h * co + j];
    U[idx] = s;
    P[idx] = scale[c] * s;
}

__global__ void cbias_k(const float* __restrict__ U, const float* __restrict__ shift,
                        float* cbias, int ci) {
    int u = threadIdx.x;
    if (u >= 64) return;
    float s = 0.f;
    for (int c = 0; c < ci; c++) s += shift[c] * U[c * 64 + u];
    cbias[u] = s;
}

// V[(h*ci+c), j] = scale[c] * W[c, h*co+j] / 32   (zero-padded to TNp cols)
__global__ void v_build(const float* __restrict__ W, const float* __restrict__ scale,
                        float* V, int ci, int co, int hco, int TNp) {
    int idx = blockIdx.x * blockDim.x + threadIdx.x;
    int K = 32 * ci;
    if (idx >= K * TNp) return;
    int kk = idx / TNp, j = idx % TNp;
    int h = kk / ci, c = kk % ci;
    V[idx] = (j < co) ? scale[c] * W[c * hco + h * co + j] * (1.0f / 32.0f) : 0.f;
}

// obias[j] = (1/32) * sum_{h,c} shift[c]*W[c,h*co+j] + b[j]
__global__ void obias_k(const float* __restrict__ W, const float* __restrict__ shift,
                        const float* __restrict__ b, float* obias, int ci, int co, int hco) {
    int j = threadIdx.x;
    if (j >= co) return;
    float s = 0.f;
    for (int h = 0; h < 32; h++)
        for (int c = 0; c < ci; c++)
            s += shift[c] * W[c * hco + h * co + j];
    obias[j] = s * (1.0f / 32.0f) + b[j];
}

// ================= CSR build =================
__global__ void deg_k(const int* __restrict__ ei, int* deg) {
    int e = blockIdx.x * blockDim.x + threadIdx.x;
    if (e >= ETOT) return;
    int d = (e < NEDGES) ? ei[NEDGES + e] : (e - NEDGES);
    atomicAdd(&deg[d], 1);
}

__global__ void scan_deg(const int* __restrict__ deg, int* rowstart) {
    __shared__ int ps[1024];
    int t = threadIdx.x;
    int base = t * 40;
    int s = 0;
    for (int i = 0; i < 40; i++) {
        int idx = base + i;
        if (idx < NNODES) s += deg[idx];
    }
    ps[t] = s;
    __syncthreads();
    for (int off = 1; off < 1024; off <<= 1) {
        int v = (t >= off) ? ps[t - off] : 0;
        __syncthreads();
        ps[t] += v;
        __syncthreads();
    }
    int run = (t > 0) ? ps[t - 1] : 0;
    for (int i = 0; i < 40; i++) {
        int idx = base + i;
        if (idx < NNODES) { rowstart[idx] = run; run += deg[idx]; }
    }
    if (t == 1023) rowstart[NNODES] = ps[1023];
}

__global__ void scatter_k(const int* __restrict__ ei, int* cursor, int* csrc) {
    int e = blockIdx.x * blockDim.x + threadIdx.x;
    if (e >= ETOT) return;
    int s, d;
    if (e < NEDGES) { s = ei[e]; d = ei[NEDGES + e]; }
    else            { s = d = e - NEDGES; }
    int pos = atomicAdd(&cursor[d], 1);
    csrc[pos] = s;
}

// ================= attention scores: S[n,64] = X @ P + cbias =================
__global__ void score_k(const float* __restrict__ X, const float* __restrict__ P,
                        const float* __restrict__ cbias, float* S, int n, int ci) {
    int idx = blockIdx.x * blockDim.x + threadIdx.x;
    int node = idx >> 4;
    int c4 = (idx & 15) * 4;
    if (node >= n) return;
    float4 acc = *((const float4*)&cbias[c4]);
    const float* xr = X + (size_t)node * ci;
    for (int k = 0; k < ci; k++) {
        float xv = xr[k];
        float4 p = *((const float4*)&P[k * 64 + c4]);
        acc.x += xv * p.x; acc.y += xv * p.y; acc.z += xv * p.z; acc.w += xv * p.w;
    }
    *((float4*)&S[(size_t)node * 64 + c4]) = acc;
}

// ================= fused softmax + aggregation (block per dst) =================
template <int CI>
__global__ void agg_k(const int* __restrict__ rowstart, const int* __restrict__ csrc,
                      const float* __restrict__ S, const float* __restrict__ X,
                      float* __restrict__ Y) {
    int d = blockIdx.x;
    int t = threadIdx.x;
    __shared__ float sm_m[32], sm_den[32], sm_alpha[32];
    int s0 = rowstart[d], s1 = rowstart[d + 1];

    if (t < 32) {
        float sd = S[(size_t)d * 64 + 32 + t];
        float m = -1e30f;
        for (int e = s0; e < s1; e++) {
            int s = csrc[e];
            float l = leaky(S[(size_t)s * 64 + t] + sd, 0.2f);
            m = fmaxf(m, l);
        }
        float den = 0.f;
        for (int e = s0; e < s1; e++) {
            int s = csrc[e];
            float l = leaky(S[(size_t)s * 64 + t] + sd, 0.2f);
            den += __expf(l - m);
        }
        sm_m[t] = m; sm_den[t] = den;
    }
    __syncthreads();

    float acc[32];
#pragma unroll
    for (int h = 0; h < 32; h++) acc[h] = 0.f;
    float sd2 = (t < 32) ? S[(size_t)d * 64 + 32 + t] : 0.f;

    for (int e = s0; e < s1; e++) {
        int s = csrc[e];
        if (t < 32) {
            float l = leaky(S[(size_t)s * 64 + t] + sd2, 0.2f);
            sm_alpha[t] = __expf(l - sm_m[t]) / sm_den[t];
        }
        __syncthreads();
        float xv = (t < CI) ? X[(size_t)s * CI + t] : 0.f;
#pragma unroll
        for (int j = 0; j < 8; j++) {
            float4 a = ((const float4*)sm_alpha)[j];
            acc[4 * j + 0] += a.x * xv;
            acc[4 * j + 1] += a.y * xv;
            acc[4 * j + 2] += a.z * xv;
            acc[4 * j + 3] += a.w * xv;
        }
        __syncthreads();
    }

    if (t < CI) {
        float* yb = Y + (size_t)d * 32 * CI + t;
#pragma unroll
        for (int h = 0; h < 32; h++) yb[h * CI] = acc[h];
    }
}

// ================= projection GEMM: act = leaky(Y[M,K] @ V[K,TN] + obias) =================
template <int TN>
__global__ __launch_bounds__(256)
void proj_gemm(const float* __restrict__ Y, const float* __restrict__ V,
               const float* __restrict__ obias, float* __restrict__ act,
               int M, int K, int co) {
    constexpr int CPT = TN / 16;                // cols per thread
    __shared__ float As[32 * 132];              // [k][m], stride 132
    __shared__ float Bs[32 * TN];               // [k][n]
    int tid = threadIdx.x;
    int gm0 = blockIdx.x * 128;
    int tx = tid & 15, ty = tid >> 4;

    float accm[8][CPT];
#pragma unroll
    for (int i = 0; i < 8; i++)
#pragma unroll
        for (int j = 0; j < CPT; j++) accm[i][j] = 0.f;

    for (int k0 = 0; k0 < K; k0 += 32) {
        // load Y tile 128x32 as float4 along K
#pragma unroll
        for (int it = 0; it < 4; it++) {
            int f = tid + it * 256;
            int m = f >> 3, k4 = (f & 7) * 4;
            int gm = gm0 + m;
            float4 v = make_float4(0.f, 0.f, 0.f, 0.f);
            if (gm < M) v = *((const float4*)&Y[(size_t)gm * K + k0 + k4]);
            As[(k4 + 0) * 132 + m] = v.x;
            As[(k4 + 1) * 132 + m] = v.y;
            As[(k4 + 2) * 132 + m] = v.z;
            As[(k4 + 3) * 132 + m] = v.w;
        }
        // load V tile 32xTN
        {
            const int numB = 32 * TN / 4;
            for (int f = tid; f < numB; f += 256) {
                int kk = f / (TN / 4), c4 = (f % (TN / 4)) * 4;
                *((float4*)&Bs[kk * TN + c4]) = *((const float4*)&V[(size_t)(k0 + kk) * TN + c4]);
            }
        }
        __syncthreads();
#pragma unroll
        for (int kk = 0; kk < 32; kk++) {
            float ar[8], br[CPT];
            *((float4*)&ar[0]) = *((const float4*)&As[kk * 132 + ty * 8]);
            *((float4*)&ar[4]) = *((const float4*)&As[kk * 132 + ty * 8 + 4]);
#pragma unroll
            for (int j = 0; j < CPT; j++) br[j] = Bs[kk * TN + tx * CPT + j];
#pragma unroll
            for (int i = 0; i < 8; i++)
#pragma unroll
                for (int j = 0; j < CPT; j++) accm[i][j] += ar[i] * br[j];
        }
        __syncthreads();
    }
#pragma unroll
    for (int i = 0; i < 8; i++) {
        int gm = gm0 + ty * 8 + i;
        if (gm >= M) continue;
#pragma unroll
        for (int j = 0; j < CPT; j++) {
            int col = tx * CPT + j;
            if (col < co) {
                float v = accm[i][j] + obias[col];
                act[(size_t)gm * co + col] = leaky(v, 0.01f);
            }
        }
    }
}

// ================= pooling + head =================
__global__ void pool_k(const float* __restrict__ act, const int* __restrict__ batch,
                       float* pool, float* cnt) {
    int nn = blockIdx.x * blockDim.x + threadIdx.x;
    if (nn >= NNODES) return;
    int gi = batch[nn];
    atomicAdd(&cnt[gi], 1.0f);
#pragma unroll
    for (int c = 0; c < 5; c++) atomicAdd(&pool[gi * 5 + c], act[nn * 5 + c]);
}

__global__ void head_k(const float* __restrict__ pool, const float* __restrict__ cnt,
                       const float* __restrict__ cond, const float* __restrict__ fcW,
                       const float* __restrict__ fcb, float* out) {
    int gi = blockIdx.x * blockDim.x + threadIdx.x;
    if (gi >= NGRAPH) return;
    float cd = 0.f;
    for (int k = 0; k < NCOND; k++) cd += cond[k] * fcW[5 + k];
    float c = fmaxf(cnt[gi], 1.0f);
    float acc = fcb[0] + cd;
#pragma unroll
    for (int j = 0; j < 5; j++) acc += (pool[gi * 5 + j] / c) * fcW[j];
    out[gi] = 1.0f / (1.0f + expf(-acc));
}

// ================= host orchestration =================
extern "C" void kernel_launch(void* const* d_in, const int* in_sizes, int n_in,
                              void* d_out, int out_size) {
    (void)in_sizes; (void)n_in; (void)out_size;
    const float* x     = (const float*)d_in[0];
    const int*   ei    = (const int*)d_in[1];
    const int*   batch = (const int*)d_in[2];
    const float* cond  = (const float*)d_in[3];
    const float* W[4]  = {(const float*)d_in[4],  (const float*)d_in[8],
                          (const float*)d_in[12], (const float*)d_in[16]};
    const float* As_[4] = {(const float*)d_in[5],  (const float*)d_in[9],
                           (const float*)d_in[13], (const float*)d_in[17]};
    const float* Ad_[4] = {(const float*)d_in[6],  (const float*)d_in[10],
                           (const float*)d_in[14], (const float*)d_in[18]};
    const float* Bb[4] = {(const float*)d_in[7],  (const float*)d_in[11],
                          (const float*)d_in[15], (const float*)d_in[19]};
    const float* G[4]  = {(const float*)d_in[20], (const float*)d_in[22],
                          (const float*)d_in[24], (const float*)d_in[26]};
    const float* Be[4] = {(const float*)d_in[21], (const float*)d_in[23],
                          (const float*)d_in[25], (const float*)d_in[27]};
    const float* fcW = (const float*)d_in[30];
    const float* fcb = (const float*)d_in[31];
    float* outp = (float*)d_out;

    float *p_Y, *p_act, *p_S, *p_U, *p_P, *p_cbias, *p_V, *p_obias;
    float *p_bnsum, *p_scale, *p_shift, *p_pool, *p_cnt;
    int *p_deg, *p_cursor, *p_rowstart, *p_csrc;
    cudaGetSymbolAddress((void**)&p_Y, g_Y);
    cudaGetSymbolAddress((void**)&p_act, g_act);
    cudaGetSymbolAddress((void**)&p_S, g_S);
    cudaGetSymbolAddress((void**)&p_U, g_U);
    cudaGetSymbolAddress((void**)&p_P, g_P);
    cudaGetSymbolAddress((void**)&p_cbias, g_cbias);
    cudaGetSymbolAddress((void**)&p_V, g_V);
    cudaGetSymbolAddress((void**)&p_obias, g_obias);
    cudaGetSymbolAddress((void**)&p_bnsum, g_bnsum);
    cudaGetSymbolAddress((void**)&p_scale, g_scale);
    cudaGetSymbolAddress((void**)&p_shift, g_shift);
    cudaGetSymbolAddress((void**)&p_pool, g_pool);
    cudaGetSymbolAddress((void**)&p_cnt, g_cnt);
    cudaGetSymbolAddress((void**)&p_deg, g_deg);
    cudaGetSymbolAddress((void**)&p_cursor, g_cursor);
    cudaGetSymbolAddress((void**)&p_rowstart, g_rowstart);
    cudaGetSymbolAddress((void**)&p_csrc, g_csrc);

    const int ci_arr[4] = {128, 90, 45, 15};
    const int co_arr[4] = {90, 45, 15, 5};
    const int tnp_arr[4] = {96, 48, 16, 16};
    const int N = NNODES;

    // ---- CSR by dst (once per call) ----
    cudaMemsetAsync(p_deg, 0, 40960 * sizeof(int), 0);
    deg_k<<<(ETOT + 255) / 256, 256>>>(ei, p_deg);
    scan_deg<<<1, 1024>>>(p_deg, p_rowstart);
    cudaMemcpyAsync(p_cursor, p_rowstart, NNODES * sizeof(int),
                    cudaMemcpyDeviceToDevice, 0);
    scatter_k<<<(ETOT + 255) / 256, 256>>>(ei, p_cursor, p_csrc);

    const float* X = x;
    for (int l = 0; l < 4; l++) {
        int ci = ci_arr[l], co = co_arr[l], hco = NHEADS * co;
        int K = 32 * ci, TNp = tnp_arr[l];

        // BN fold
        cudaMemsetAsync(p_bnsum, 0, 2 * ci * sizeof(float), 0);
        {
            int bdim = ((ci + 31) / 32) * 32;
            bn_accum<<<(N + 255) / 256, bdim>>>(X, N, ci, p_bnsum);
        }
        bn_final<<<1, 128>>>(p_bnsum, G[l], Be[l], p_scale, p_shift, N, ci);

        // parameter prep
        p_build<<<(ci * 64 + 255) / 256, 256>>>(W[l], As_[l], Ad_[l], p_scale, p_U, p_P, ci, co, hco);
        cbias_k<<<1, 64>>>(p_U, p_shift, p_cbias, ci);
        v_build<<<(K * TNp + 255) / 256, 256>>>(W[l], p_scale, p_V, ci, co, hco, TNp);
        obias_k<<<1, ((co + 31) / 32) * 32>>>(W[l], p_shift, Bb[l], p_obias, ci, co, hco);

        // attention scores
        score_k<<<(N * 16 + 255) / 256, 256>>>(X, p_P, p_cbias, p_S, N, ci);

        // fused softmax + aggregation into Y [N, 32*ci]
        switch (l) {
            case 0: agg_k<128><<<N, 128>>>(p_rowstart, p_csrc, p_S, X, p_Y); break;
            case 1: agg_k<90><<<N, 96>>>(p_rowstart, p_csrc, p_S, X, p_Y); break;
            case 2: agg_k<45><<<N, 64>>>(p_rowstart, p_csrc, p_S, X, p_Y); break;
            case 3: agg_k<15><<<N, 32>>>(p_rowstart, p_csrc, p_S, X, p_Y); break;
        }

        // projection GEMM with leaky epilogue
        int gblocks = (N + 127) / 128;
        switch (l) {
            case 0: proj_gemm<96><<<gblocks, 256>>>(p_Y, p_V, p_obias, p_act, N, K, co); break;
            case 1: proj_gemm<48><<<gblocks, 256>>>(p_Y, p_V, p_obias, p_act, N, K, co); break;
            case 2: proj_gemm<16><<<gblocks, 256>>>(p_Y, p_V, p_obias, p_act, N, K, co); break;
            case 3: proj_gemm<16><<<gblocks, 256>>>(p_Y, p_V, p_obias, p_act, N, K, co); break;
        }
        X = p_act;
    }

    // pooling + head
    cudaMemsetAsync(p_pool, 0, NGRAPH * 5 * sizeof(float), 0);
    cudaMemsetAsync(p_cnt, 0, NGRAPH * sizeof(float), 0);
    pool_k<<<(NNODES + 255) / 256, 256>>>(p_act, batch, p_pool, p_cnt);
    head_k<<<1, 256>>>(p_pool, p_cnt, cond, fcW, fcb, outp);
}

// round 4
// speedup vs baseline: 2.6925x; 1.9393x over previous
#include <cuda_runtime.h>
#include <cuda_fp16.h>
#include <cstdint>
#include <math.h>

#define NNODES 40000
#define NEDGES 400000
#define ETOT   (NEDGES + NNODES)
#define NHEADS 32
#define NGRAPH 256
#define NCOND  100
#define BN_EPS 1e-5f

// ---------------- scratch ----------------
__device__ float g_Y[81920000];           // fp16 Y plane [N, 4096] max (327MB)
__device__ float g_act[NNODES * 90];
__device__ float g_S[NNODES * 64];
__device__ float g_U[128 * 64];
__device__ float g_P[128 * 64];
__device__ float g_cbias[64];
__device__ float g_V[4096 * 96];          // fp16 Vt plane [NP, Kp]
__device__ float g_obias[96];
__device__ float g_bnsum[2 * 128];
__device__ float g_scale[128];
__device__ float g_shift[128];
__device__ int   g_deg[40960];
__device__ int   g_cursor[40960];
__device__ int   g_rowstart[NNODES + 1];
__device__ int   g_csrc[ETOT];
__device__ float g_pool[NGRAPH * 5];
__device__ float g_cnt[NGRAPH];

__device__ __forceinline__ float leaky(float v, float s) { return v > 0.f ? v : s * v; }

__device__ __forceinline__ uint32_t smem_u32(const void* p) {
    uint32_t a;
    asm("{ .reg .u64 t; cvta.to.shared.u64 t, %1; cvt.u32.u64 %0, t; }" : "=r"(a) : "l"(p));
    return a;
}

// ================= BatchNorm stats =================
__global__ void bn_accum(const float* __restrict__ X, int n, int ci, float* sums) {
    int col = threadIdx.x;
    if (col >= ci) return;
    int r0 = blockIdx.x * 256;
    int r1 = r0 + 256; if (r1 > n) r1 = n;
    float s = 0.f, s2 = 0.f;
    for (int r = r0; r < r1; r++) {
        float v = X[r * ci + col];
        s += v; s2 += v * v;
    }
    atomicAdd(&sums[col], s);
    atomicAdd(&sums[ci + col], s2);
}

__global__ void bn_final(const float* sums, const float* __restrict__ g,
                         const float* __restrict__ be, float* scale, float* shift,
                         int n, int ci) {
    int c = blockIdx.x * blockDim.x + threadIdx.x;
    if (c >= ci) return;
    float mu  = sums[c] / (float)n;
    float var = sums[ci + c] / (float)n - mu * mu;
    float rs  = rsqrtf(var + BN_EPS);
    float sc  = g[c] * rs;
    scale[c] = sc;
    shift[c] = be[c] - mu * sc;
}

// ================= parameter preprocessing =================
__global__ void p_build(const float* __restrict__ W, const float* __restrict__ as_,
                        const float* __restrict__ ad_, const float* __restrict__ scale,
                        float* U, float* P, int ci, int co, int hco) {
    int idx = blockIdx.x * blockDim.x + threadIdx.x;
    if (idx >= ci * 64) return;
    int c = idx >> 6, u = idx & 63;
    int h = u & 31;
    const float* a = (u < 32) ? as_ : ad_;
    float s = 0.f;
    for (int j = 0; j < co; j++) s += W[c * hco + h * co + j] * a[h * co + j];
    U[idx] = s;
    P[idx] = scale[c] * s;
}

__global__ void cbias_k(const float* __restrict__ U, const float* __restrict__ shift,
                        float* cbias, int ci) {
    int u = threadIdx.x;
    if (u >= 64) return;
    float s = 0.f;
    for (int c = 0; c < ci; c++) s += shift[c] * U[c * 64 + u];
    cbias[u] = s;
}

// Vt[j, h*ci + c] = scale[c]*W[c,h*co+j]/32 in fp16 (zeros in padding)
__global__ void vt_build(const float* __restrict__ W, const float* __restrict__ scale,
                         __half* Vt, int ci, int co, int hco, int NP, int K, int Kp) {
    int idx = blockIdx.x * blockDim.x + threadIdx.x;
    if (idx >= NP * Kp) return;
    int j = idx / Kp, k = idx % Kp;
    float v = 0.f;
    if (j < co && k < K) {
        int h = k / ci, c = k % ci;
        v = scale[c] * W[c * hco + h * co + j] * (1.0f / 32.0f);
    }
    Vt[idx] = __float2half(v);
}

__global__ void obias_k(const float* __restrict__ W, const float* __restrict__ shift,
                        const float* __restrict__ b, float* obias, int ci, int co, int hco) {
    int j = threadIdx.x;
    if (j >= co) return;
    float s = 0.f;
    for (int h = 0; h < 32; h++)
        for (int c = 0; c < ci; c++)
            s += shift[c] * W[c * hco + h * co + j];
    obias[j] = s * (1.0f / 32.0f) + b[j];
}

// ================= CSR build =================
__global__ void deg_k(const int* __restrict__ ei, int* deg) {
    int e = blockIdx.x * blockDim.x + threadIdx.x;
    if (e >= ETOT) return;
    int d = (e < NEDGES) ? ei[NEDGES + e] : (e - NEDGES);
    atomicAdd(&deg[d], 1);
}

__global__ void scan_deg(const int* __restrict__ deg, int* rowstart) {
    __shared__ int ps[1024];
    int t = threadIdx.x;
    int base = t * 40;
    int s = 0;
    for (int i = 0; i < 40; i++) {
        int idx = base + i;
        if (idx < NNODES) s += deg[idx];
    }
    ps[t] = s;
    __syncthreads();
    for (int off = 1; off < 1024; off <<= 1) {
        int v = (t >= off) ? ps[t - off] : 0;
        __syncthreads();
        ps[t] += v;
        __syncthreads();
    }
    int run = (t > 0) ? ps[t - 1] : 0;
    for (int i = 0; i < 40; i++) {
        int idx = base + i;
        if (idx < NNODES) { rowstart[idx] = run; run += deg[idx]; }
    }
    if (t == 1023) rowstart[NNODES] = ps[1023];
}

__global__ void scatter_k(const int* __restrict__ ei, int* cursor, int* csrc) {
    int e = blockIdx.x * blockDim.x + threadIdx.x;
    if (e >= ETOT) return;
    int s, d;
    if (e < NEDGES) { s = ei[e]; d = ei[NEDGES + e]; }
    else            { s = d = e - NEDGES; }
    int pos = atomicAdd(&cursor[d], 1);
    csrc[pos] = s;
}

// ================= attention scores =================
__global__ void score_k(const float* __restrict__ X, const float* __restrict__ P,
                        const float* __restrict__ cbias, float* S, int n, int ci) {
    int idx = blockIdx.x * blockDim.x + threadIdx.x;
    int node = idx >> 4;
    int c4 = (idx & 15) * 4;
    if (node >= n) return;
    float4 acc = *((const float4*)&cbias[c4]);
    const float* xr = X + (size_t)node * ci;
    for (int k = 0; k < ci; k++) {
        float xv = xr[k];
        float4 p = *((const float4*)&P[k * 64 + c4]);
        acc.x += xv * p.x; acc.y += xv * p.y; acc.z += xv * p.z; acc.w += xv * p.w;
    }
    *((float4*)&S[(size_t)node * 64 + c4]) = acc;
}

// ================= fused softmax + aggregation -> fp16 Y =================
template <int CI>
__global__ void agg_k(const int* __restrict__ rowstart, const int* __restrict__ csrc,
                      const float* __restrict__ S, const float* __restrict__ X,
                      __half* __restrict__ Yh, int Kp) {
    int d = blockIdx.x;
    int t = threadIdx.x;
    __shared__ float sm_m[32], sm_den[32], sm_alpha[32];
    int s0 = rowstart[d], s1 = rowstart[d + 1];

    if (t < 32) {
        float sd = S[(size_t)d * 64 + 32 + t];
        float m = -1e30f;
        for (int e = s0; e < s1; e++) {
            int s = csrc[e];
            float l = leaky(S[(size_t)s * 64 + t] + sd, 0.2f);
            m = fmaxf(m, l);
        }
        float den = 0.f;
        for (int e = s0; e < s1; e++) {
            int s = csrc[e];
            float l = leaky(S[(size_t)s * 64 + t] + sd, 0.2f);
            den += __expf(l - m);
        }
        sm_m[t] = m; sm_den[t] = den;
    }
    __syncthreads();

    float acc[32];
#pragma unroll
    for (int h = 0; h < 32; h++) acc[h] = 0.f;
    float sd2 = (t < 32) ? S[(size_t)d * 64 + 32 + t] : 0.f;

    for (int e = s0; e < s1; e++) {
        int s = csrc[e];
        if (t < 32) {
            float l = leaky(S[(size_t)s * 64 + t] + sd2, 0.2f);
            sm_alpha[t] = __expf(l - sm_m[t]) / sm_den[t];
        }
        __syncthreads();
        float xv = (t < CI) ? X[(size_t)s * CI + t] : 0.f;
#pragma unroll
        for (int j = 0; j < 8; j++) {
            float4 a = ((const float4*)sm_alpha)[j];
            acc[4 * j + 0] += a.x * xv;
            acc[4 * j + 1] += a.y * xv;
            acc[4 * j + 2] += a.z * xv;
            acc[4 * j + 3] += a.w * xv;
        }
        __syncthreads();
    }

    size_t rb = (size_t)d * Kp;
    if (t < CI) {
#pragma unroll
        for (int h = 0; h < 32; h++)
            Yh[rb + h * CI + t] = __float2half(acc[h]);
    }
    const int K = 32 * CI;
    __half z = __float2half(0.f);
    for (int q = K + t; q < Kp; q += blockDim.x) Yh[rb + q] = z;
}

// ================= HMMA projection: act = leaky(Y@Vt^T + obias) =================
// Y [M, Kp] fp16 row-major, Vt [NP, Kp] fp16 (n-major rows => col-major B frags)
template <int NP, int CO>
__global__ __launch_bounds__(256)
void proj_mma(const __half* __restrict__ A, const __half* __restrict__ B,
              const float* __restrict__ obias, float* __restrict__ act,
              int M, int Kp) {
    constexpr int NB2 = NP / 8;    // mma n8 blocks
    constexpr int NB4 = NP / 16;   // ldmatrix x4 groups (n16)
    __shared__ __half As[128][72];
    __shared__ __half Bs[NP][72];
    int tid = threadIdx.x;
    int w = tid >> 5, l = tid & 31;
    int gm0 = blockIdx.x * 128;
    int lr = l & 7, grp = l >> 3;

    float acc[NB2][4];
#pragma unroll
    for (int f = 0; f < NB2; f++)
#pragma unroll
        for (int q = 0; q < 4; q++) acc[f][q] = 0.f;

    uint32_t as_base = smem_u32(&As[0][0]);
    uint32_t bs_base = smem_u32(&Bs[0][0]);

    // A frag smem addr components (per warp)
    int a_row = w * 16 + lr + ((grp & 1) ? 8 : 0);
    int a_colofs = (grp & 2) ? 8 : 0;
    // B frag addr components
    int b_rowofs = lr + ((grp >= 2) ? 8 : 0);
    int b_colofs = (grp & 1) ? 8 : 0;

    for (int k0 = 0; k0 < Kp; k0 += 64) {
        // ---- load A tile: 128 x 64 halfs ----
#pragma unroll
        for (int it = 0; it < 4; it++) {
            int f = tid + it * 256;
            int row = f >> 3, seg = f & 7;
            int gm = gm0 + row;
            uint4 v = make_uint4(0, 0, 0, 0);
            if (gm < M) v = *(const uint4*)(A + (size_t)gm * Kp + k0 + seg * 8);
            *(uint4*)(&As[row][seg * 8]) = v;
        }
        // ---- load B tile: NP x 64 halfs ----
        for (int q = tid; q < NP * 8; q += 256) {
            int row = q >> 3, seg = q & 7;
            *(uint4*)(&Bs[row][seg * 8]) =
                *(const uint4*)(B + (size_t)row * Kp + k0 + seg * 8);
        }
        __syncthreads();

#pragma unroll
        for (int kb = 0; kb < 64; kb += 16) {
            uint32_t a0, a1, a2, a3;
            {
                uint32_t addr = as_base + (a_row * 72 + kb + a_colofs) * 2;
                asm volatile("ldmatrix.sync.aligned.m8n8.x4.shared.b16 {%0,%1,%2,%3}, [%4];"
                             : "=r"(a0), "=r"(a1), "=r"(a2), "=r"(a3) : "r"(addr));
            }
#pragma unroll
            for (int j4 = 0; j4 < NB4; j4++) {
                uint32_t b0, b1, b2, b3;
                uint32_t addr = bs_base + ((j4 * 16 + b_rowofs) * 72 + kb + b_colofs) * 2;
                asm volatile("ldmatrix.sync.aligned.m8n8.x4.shared.b16 {%0,%1,%2,%3}, [%4];"
                             : "=r"(b0), "=r"(b1), "=r"(b2), "=r"(b3) : "r"(addr));
                asm volatile("mma.sync.aligned.m16n8k16.row.col.f32.f16.f16.f32 "
                             "{%0,%1,%2,%3}, {%4,%5,%6,%7}, {%8,%9}, {%0,%1,%2,%3};"
                             : "+f"(acc[2 * j4][0]), "+f"(acc[2 * j4][1]),
                               "+f"(acc[2 * j4][2]), "+f"(acc[2 * j4][3])
                             : "r"(a0), "r"(a1), "r"(a2), "r"(a3), "r"(b0), "r"(b1));
                asm volatile("mma.sync.aligned.m16n8k16.row.col.f32.f16.f16.f32 "
                             "{%0,%1,%2,%3}, {%4,%5,%6,%7}, {%8,%9}, {%0,%1,%2,%3};"
                             : "+f"(acc[2 * j4 + 1][0]), "+f"(acc[2 * j4 + 1][1]),
                               "+f"(acc[2 * j4 + 1][2]), "+f"(acc[2 * j4 + 1][3])
                             : "r"(a0), "r"(a1), "r"(a2), "r"(a3), "r"(b2), "r"(b3));
            }
        }
        __syncthreads();
    }

    // ---- epilogue ----
    int r = l >> 2, cg = l & 3;
    int row0 = gm0 + w * 16 + r;
    int row1 = row0 + 8;
#pragma unroll
    for (int f = 0; f < NB2; f++) {
        int c = f * 8 + 2 * cg;
        if (c < CO) {
            if (row0 < M) {
                float v0 = acc[f][0] + obias[c];
                act[(size_t)row0 * CO + c] = leaky(v0, 0.01f);
                if (c + 1 < CO) {
                    float v1 = acc[f][1] + obias[c + 1];
                    act[(size_t)row0 * CO + c + 1] = leaky(v1, 0.01f);
                }
            }
            if (row1 < M) {
                float v2 = acc[f][2] + obias[c];
                act[(size_t)row1 * CO + c] = leaky(v2, 0.01f);
                if (c + 1 < CO) {
                    float v3 = acc[f][3] + obias[c + 1];
                    act[(size_t)row1 * CO + c + 1] = leaky(v3, 0.01f);
                }
            }
        }
    }
}

// ================= pooling + head =================
__global__ void pool_k(const float* __restrict__ act, const int* __restrict__ batch,
                       float* pool, float* cnt) {
    int nn = blockIdx.x * blockDim.x + threadIdx.x;
    if (nn >= NNODES) return;
    int gi = batch[nn];
    atomicAdd(&cnt[gi], 1.0f);
#pragma unroll
    for (int c = 0; c < 5; c++) atomicAdd(&pool[gi * 5 + c], act[nn * 5 + c]);
}

__global__ void head_k(const float* __restrict__ pool, const float* __restrict__ cnt,
                       const float* __restrict__ cond, const float* __restrict__ fcW,
                       const float* __restrict__ fcb, float* out) {
    int gi = blockIdx.x * blockDim.x + threadIdx.x;
    if (gi >= NGRAPH) return;
    float cd = 0.f;
    for (int k = 0; k < NCOND; k++) cd += cond[k] * fcW[5 + k];
    float c = fmaxf(cnt[gi], 1.0f);
    float acc = fcb[0] + cd;
#pragma unroll
    for (int j = 0; j < 5; j++) acc += (pool[gi * 5 + j] / c) * fcW[j];
    out[gi] = 1.0f / (1.0f + expf(-acc));
}

// ================= host orchestration =================
extern "C" void kernel_launch(void* const* d_in, const int* in_sizes, int n_in,
                              void* d_out, int out_size) {
    (void)in_sizes; (void)n_in; (void)out_size;
    const float* x     = (const float*)d_in[0];
    const int*   ei    = (const int*)d_in[1];
    const int*   batch = (const int*)d_in[2];
    const float* cond  = (const float*)d_in[3];
    const float* W[4]  = {(const float*)d_in[4],  (const float*)d_in[8],
                          (const float*)d_in[12], (const float*)d_in[16]};
    const float* As_[4] = {(const float*)d_in[5],  (const float*)d_in[9],
                           (const float*)d_in[13], (const float*)d_in[17]};
    const float* Ad_[4] = {(const float*)d_in[6],  (const float*)d_in[10],
                           (const float*)d_in[14], (const float*)d_in[18]};
    const float* Bb[4] = {(const float*)d_in[7],  (const float*)d_in[11],
                          (const float*)d_in[15], (const float*)d_in[19]};
    const float* G[4]  = {(const float*)d_in[20], (const float*)d_in[22],
                          (const float*)d_in[24], (const float*)d_in[26]};
    const float* Be[4] = {(const float*)d_in[21], (const float*)d_in[23],
                          (const float*)d_in[25], (const float*)d_in[27]};
    const float* fcW = (const float*)d_in[30];
    const float* fcb = (const float*)d_in[31];
    float* outp = (float*)d_out;

    float *p_Y, *p_act, *p_S, *p_U, *p_P, *p_cbias, *p_V, *p_obias;
    float *p_bnsum, *p_scale, *p_shift, *p_pool, *p_cnt;
    int *p_deg, *p_cursor, *p_rowstart, *p_csrc;
    cudaGetSymbolAddress((void**)&p_Y, g_Y);
    cudaGetSymbolAddress((void**)&p_act, g_act);
    cudaGetSymbolAddress((void**)&p_S, g_S);
    cudaGetSymbolAddress((void**)&p_U, g_U);
    cudaGetSymbolAddress((void**)&p_P, g_P);
    cudaGetSymbolAddress((void**)&p_cbias, g_cbias);
    cudaGetSymbolAddress((void**)&p_V, g_V);
    cudaGetSymbolAddress((void**)&p_obias, g_obias);
    cudaGetSymbolAddress((void**)&p_bnsum, g_bnsum);
    cudaGetSymbolAddress((void**)&p_scale, g_scale);
    cudaGetSymbolAddress((void**)&p_shift, g_shift);
    cudaGetSymbolAddress((void**)&p_pool, g_pool);
    cudaGetSymbolAddress((void**)&p_cnt, g_cnt);
    cudaGetSymbolAddress((void**)&p_deg, g_deg);
    cudaGetSymbolAddress((void**)&p_cursor, g_cursor);
    cudaGetSymbolAddress((void**)&p_rowstart, g_rowstart);
    cudaGetSymbolAddress((void**)&p_csrc, g_csrc);

    __half* Yh = (__half*)p_Y;
    __half* Vt = (__half*)p_V;

    const int ci_arr[4] = {128, 90, 45, 15};
    const int co_arr[4] = {90, 45, 15, 5};
    const int np_arr[4] = {96, 48, 16, 16};
    const int kp_arr[4] = {4096, 2880, 1472, 512};
    const int N = NNODES;

    // ---- CSR by dst ----
    cudaMemsetAsync(p_deg, 0, 40960 * sizeof(int), 0);
    deg_k<<<(ETOT + 255) / 256, 256>>>(ei, p_deg);
    scan_deg<<<1, 1024>>>(p_deg, p_rowstart);
    cudaMemcpyAsync(p_cursor, p_rowstart, NNODES * sizeof(int),
                    cudaMemcpyDeviceToDevice, 0);
    scatter_k<<<(ETOT + 255) / 256, 256>>>(ei, p_cursor, p_csrc);

    const float* X = x;
    for (int l = 0; l < 4; l++) {
        int ci = ci_arr[l], co = co_arr[l], hco = NHEADS * co;
        int K = 32 * ci, Kp = kp_arr[l], NP = np_arr[l];

        // BN fold
        cudaMemsetAsync(p_bnsum, 0, 2 * ci * sizeof(float), 0);
        {
            int bdim = ((ci + 31) / 32) * 32;
            bn_accum<<<(N + 255) / 256, bdim>>>(X, N, ci, p_bnsum);
        }
        bn_final<<<1, 128>>>(p_bnsum, G[l], Be[l], p_scale, p_shift, N, ci);

        // parameter prep
        p_build<<<(ci * 64 + 255) / 256, 256>>>(W[l], As_[l], Ad_[l], p_scale, p_U, p_P, ci, co, hco);
        cbias_k<<<1, 64>>>(p_U, p_shift, p_cbias, ci);
        vt_build<<<(NP * Kp + 255) / 256, 256>>>(W[l], p_scale, Vt, ci, co, hco, NP, K, Kp);
        obias_k<<<1, ((co + 31) / 32) * 32>>>(W[l], p_shift, Bb[l], p_obias, ci, co, hco);

        // attention scores
        score_k<<<(N * 16 + 255) / 256, 256>>>(X, p_P, p_cbias, p_S, N, ci);

        // fused softmax + aggregation into fp16 Y [N, Kp]
        switch (l) {
            case 0: agg_k<128><<<N, 128>>>(p_rowstart, p_csrc, p_S, X, Yh, Kp); break;
            case 1: agg_k<90><<<N, 96>>>(p_rowstart, p_csrc, p_S, X, Yh, Kp); break;
            case 2: agg_k<45><<<N, 64>>>(p_rowstart, p_csrc, p_S, X, Yh, Kp); break;
            case 3: agg_k<15><<<N, 32>>>(p_rowstart, p_csrc, p_S, X, Yh, Kp); break;
        }

        // HMMA projection GEMM with leaky epilogue
        int gblocks = (N + 127) / 128;
        switch (l) {
            case 0: proj_mma<96, 90><<<gblocks, 256>>>(Yh, Vt, p_obias, p_act, N, Kp); break;
            case 1: proj_mma<48, 45><<<gblocks, 256>>>(Yh, Vt, p_obias, p_act, N, Kp); break;
            case 2: proj_mma<16, 15><<<gblocks, 256>>>(Yh, Vt, p_obias, p_act, N, Kp); break;
            case 3: proj_mma<16, 5><<<gblocks, 256>>>(Yh, Vt, p_obias, p_act, N, Kp); break;
        }
        X = p_act;
    }

    // pooling + head
    cudaMemsetAsync(p_pool, 0, NGRAPH * 5 * sizeof(float), 0);
    cudaMemsetAsync(p_cnt, 0, NGRAPH * sizeof(float), 0);
    pool_k<<<(NNODES + 255) / 256, 256>>>(p_act, batch, p_pool, p_cnt);
    head_k<<<1, 256>>>(p_pool, p_cnt, cond, fcW, fcb, outp);
}

// round 5
// speedup vs baseline: 3.5357x; 1.3132x over previous
#include <cuda_runtime.h>
#include <cuda_fp16.h>
#include <cstdint>
#include <math.h>

#define NNODES 40000
#define NEDGES 400000
#define ETOT   (NEDGES + NNODES)
#define NHEADS 32
#define NGRAPH 256
#define NCOND  100
#define BN_EPS 1e-5f

// ---------------- scratch ----------------
__device__ float g_Y[81920000];           // fp16 Y plane [N, 4096] max (327MB)
__device__ float g_act[NNODES * 90];
__device__ float g_S[NNODES * 64];
__device__ float g_U[128 * 64];
__device__ float g_P[128 * 64];
__device__ float g_cbias[64];
__device__ float g_V[4096 * 96];          // fp16 Vt plane [NP, Kp]
__device__ float g_obias[96];
__device__ float g_bnsum[2 * 128];
__device__ float g_scale[128];
__device__ float g_shift[128];
__device__ int   g_deg[40960];
__device__ int   g_cursor[40960];
__device__ int   g_rowstart[NNODES + 1];
__device__ int   g_csrc[ETOT];
__device__ float g_pool[NGRAPH * 5];
__device__ float g_cnt[NGRAPH];

__device__ __forceinline__ float leaky(float v, float s) { return v > 0.f ? v : s * v; }

__device__ __forceinline__ uint32_t smem_u32(const void* p) {
    uint32_t a;
    asm("{ .reg .u64 t; cvta.to.shared.u64 t, %1; cvt.u32.u64 %0, t; }" : "=r"(a) : "l"(p));
    return a;
}

#define CP_A16(dst, src, sz) \
    asm volatile("cp.async.cg.shared.global [%0], [%1], 16, %2;" \
                 :: "r"(dst), "l"(src), "r"(sz) : "memory")
#define CP_COMMIT() asm volatile("cp.async.commit_group;" ::: "memory")
#define CP_WAIT1()  asm volatile("cp.async.wait_group 1;" ::: "memory")
#define CP_WAIT0()  asm volatile("cp.async.wait_group 0;" ::: "memory")

// ================= BatchNorm stats =================
__global__ void bn_accum(const float* __restrict__ X, int n, int ci, float* sums) {
    int col = threadIdx.x;
    if (col >= ci) return;
    int r0 = blockIdx.x * 256;
    int r1 = r0 + 256; if (r1 > n) r1 = n;
    float s = 0.f, s2 = 0.f;
    int r = r0;
    for (; r + 4 <= r1; r += 4) {
        float v0 = X[(r + 0) * ci + col];
        float v1 = X[(r + 1) * ci + col];
        float v2 = X[(r + 2) * ci + col];
        float v3 = X[(r + 3) * ci + col];
        s += (v0 + v1) + (v2 + v3);
        s2 += v0 * v0 + v1 * v1 + v2 * v2 + v3 * v3;
    }
    for (; r < r1; r++) { float v = X[r * ci + col]; s += v; s2 += v * v; }
    atomicAdd(&sums[col], s);
    atomicAdd(&sums[ci + col], s2);
}

__global__ void bn_final(const float* sums, const float* __restrict__ g,
                         const float* __restrict__ be, float* scale, float* shift,
                         int n, int ci) {
    int c = blockIdx.x * blockDim.x + threadIdx.x;
    if (c >= ci) return;
    float mu  = sums[c] / (float)n;
    float var = sums[ci + c] / (float)n - mu * mu;
    float rs  = rsqrtf(var + BN_EPS);
    float sc  = g[c] * rs;
    scale[c] = sc;
    shift[c] = be[c] - mu * sc;
}

// ================= parameter preprocessing =================
__global__ void p_build(const float* __restrict__ W, const float* __restrict__ as_,
                        const float* __restrict__ ad_, const float* __restrict__ scale,
                        float* U, float* P, int ci, int co, int hco) {
    int idx = blockIdx.x * blockDim.x + threadIdx.x;
    if (idx >= ci * 64) return;
    int c = idx >> 6, u = idx & 63;
    int h = u & 31;
    const float* a = (u < 32) ? as_ : ad_;
    float s = 0.f;
    for (int j = 0; j < co; j++) s += W[c * hco + h * co + j] * a[h * co + j];
    U[idx] = s;
    P[idx] = scale[c] * s;
}

__global__ void cbias_k(const float* __restrict__ U, const float* __restrict__ shift,
                        float* cbias, int ci) {
    int u = threadIdx.x;
    if (u >= 64) return;
    float s = 0.f;
    for (int c = 0; c < ci; c++) s += shift[c] * U[c * 64 + u];
    cbias[u] = s;
}

// Vt[j, h*ci + c] = scale[c]*W[c,h*co+j]/32 in fp16 (zeros in padding)
__global__ void vt_build(const float* __restrict__ W, const float* __restrict__ scale,
                         __half* Vt, int ci, int co, int hco, int NP, int K, int Kp) {
    int idx = blockIdx.x * blockDim.x + threadIdx.x;
    if (idx >= NP * Kp) return;
    int j = idx / Kp, k = idx % Kp;
    float v = 0.f;
    if (j < co && k < K) {
        int h = k / ci, c = k % ci;
        v = scale[c] * W[c * hco + h * co + j] * (1.0f / 32.0f);
    }
    Vt[idx] = __float2half(v);
}

// block per output column j: reduce over h,c
__global__ void obias_k(const float* __restrict__ W, const float* __restrict__ shift,
                        const float* __restrict__ b, float* obias, int ci, int co, int hco) {
    int j = blockIdx.x;
    if (j >= co) return;
    int t = threadIdx.x;
    __shared__ float red[256];
    float s = 0.f;
    int tot = 32 * ci;
    for (int q = t; q < tot; q += 256) {
        int h = q / ci, c = q % ci;
        s += shift[c] * W[c * hco + h * co + j];
    }
    red[t] = s;
    __syncthreads();
    for (int off = 128; off; off >>= 1) {
        if (t < off) red[t] += red[t + off];
        __syncthreads();
    }
    if (t == 0) obias[j] = red[0] * (1.0f / 32.0f) + b[j];
}

// ================= CSR build =================
__global__ void deg_k(const int* __restrict__ ei, int* deg) {
    int e = blockIdx.x * blockDim.x + threadIdx.x;
    if (e >= ETOT) return;
    int d = (e < NEDGES) ? ei[NEDGES + e] : (e - NEDGES);
    atomicAdd(&deg[d], 1);
}

__global__ void scan_deg(const int* __restrict__ deg, int* rowstart) {
    __shared__ int ps[1024];
    int t = threadIdx.x;
    int base = t * 40;
    int s = 0;
    for (int i = 0; i < 40; i++) {
        int idx = base + i;
        if (idx < NNODES) s += deg[idx];
    }
    ps[t] = s;
    __syncthreads();
    for (int off = 1; off < 1024; off <<= 1) {
        int v = (t >= off) ? ps[t - off] : 0;
        __syncthreads();
        ps[t] += v;
        __syncthreads();
    }
    int run = (t > 0) ? ps[t - 1] : 0;
    for (int i = 0; i < 40; i++) {
        int idx = base + i;
        if (idx < NNODES) { rowstart[idx] = run; run += deg[idx]; }
    }
    if (t == 1023) rowstart[NNODES] = ps[1023];
}

__global__ void scatter_k(const int* __restrict__ ei, int* cursor, int* csrc) {
    int e = blockIdx.x * blockDim.x + threadIdx.x;
    if (e >= ETOT) return;
    int s, d;
    if (e < NEDGES) { s = ei[e]; d = ei[NEDGES + e]; }
    else            { s = d = e - NEDGES; }
    int pos = atomicAdd(&cursor[d], 1);
    csrc[pos] = s;
}

// ================= attention scores =================
__global__ void score_k(const float* __restrict__ X, const float* __restrict__ P,
                        const float* __restrict__ cbias, float* S, int n, int ci) {
    int idx = blockIdx.x * blockDim.x + threadIdx.x;
    int node = idx >> 4;
    int c4 = (idx & 15) * 4;
    if (node >= n) return;
    float4 acc = *((const float4*)&cbias[c4]);
    const float* xr = X + (size_t)node * ci;
    for (int k = 0; k < ci; k++) {
        float xv = xr[k];
        float4 p = *((const float4*)&P[k * 64 + c4]);
        acc.x += xv * p.x; acc.y += xv * p.y; acc.z += xv * p.z; acc.w += xv * p.w;
    }
    *((float4*)&S[(size_t)node * 64 + c4]) = acc;
}

// ================= fused softmax + aggregation (4-edge batches) =================
template <int CI>
__global__ __launch_bounds__(128)
void agg_k(const int* __restrict__ rowstart, const int* __restrict__ csrc,
           const float* __restrict__ S, const float* __restrict__ X,
           __half* __restrict__ Yh, int Kp) {
    int d = blockIdx.x;
    int t = threadIdx.x;
    int grp = t >> 5, hh = t & 31;
    __shared__ float red[4][32];
    __shared__ float sm_m[32], sm_den[32];
    __shared__ float sm_alpha[4][32];
    __shared__ int   sm_src[4];
    int s0 = rowstart[d], s1 = rowstart[d + 1];

    float sdv = S[(size_t)d * 64 + 32 + hh];

    // pass 1: max (4-way parallel over edges)
    {
        float m = -1e30f;
        for (int e = s0 + grp; e < s1; e += 4) {
            int s = csrc[e];
            m = fmaxf(m, leaky(S[(size_t)s * 64 + hh] + sdv, 0.2f));
        }
        red[grp][hh] = m;
        __syncthreads();
        if (grp == 0) {
            float mm = fmaxf(fmaxf(red[0][hh], red[1][hh]), fmaxf(red[2][hh], red[3][hh]));
            sm_m[hh] = mm;
        }
        __syncthreads();
    }
    // pass 2: denom
    {
        float mv = sm_m[hh];
        float den = 0.f;
        for (int e = s0 + grp; e < s1; e += 4) {
            int s = csrc[e];
            float l = leaky(S[(size_t)s * 64 + hh] + sdv, 0.2f);
            den += __expf(l - mv);
        }
        red[grp][hh] = den;
        __syncthreads();
        if (grp == 0) {
            sm_den[hh] = (red[0][hh] + red[1][hh]) + (red[2][hh] + red[3][hh]);
        }
        __syncthreads();
    }

    float acc[32];
#pragma unroll
    for (int h = 0; h < 32; h++) acc[h] = 0.f;
    float mv = sm_m[hh], dv = sm_den[hh];

    for (int eb = s0; eb < s1; eb += 4) {
        int ne = s1 - eb; if (ne > 4) ne = 4;
        if (grp < ne) {
            int s = csrc[eb + grp];
            if (hh == 0) sm_src[grp] = s;
            float l = leaky(S[(size_t)s * 64 + hh] + sdv, 0.2f);
            sm_alpha[grp][hh] = __expf(l - mv) / dv;
        }
        __syncthreads();
#pragma unroll 4
        for (int q = 0; q < 4; q++) {
            if (q >= ne) break;
            int s = sm_src[q];
            float xv = (t < CI) ? X[(size_t)s * CI + t] : 0.f;
#pragma unroll
            for (int j = 0; j < 8; j++) {
                float4 a = ((const float4*)sm_alpha[q])[j];
                acc[4 * j + 0] += a.x * xv;
                acc[4 * j + 1] += a.y * xv;
                acc[4 * j + 2] += a.z * xv;
                acc[4 * j + 3] += a.w * xv;
            }
        }
        __syncthreads();
    }

    size_t rb = (size_t)d * Kp;
    if (t < CI) {
#pragma unroll
        for (int h = 0; h < 32; h++)
            Yh[rb + h * CI + t] = __float2half(acc[h]);
    }
    const int K = 32 * CI;
    __half z = __float2half(0.f);
    for (int q = K + t; q < Kp; q += 128) Yh[rb + q] = z;
}

// ================= HMMA projection with cp.async double buffer =================
// Y [M, Kp] fp16 row-major, Vt [NP, Kp] fp16 (n-major rows => col-major B frags)
template <int NP, int CO>
__global__ __launch_bounds__(256)
void proj_mma(const __half* __restrict__ A, const __half* __restrict__ B,
              const float* __restrict__ obias, float* __restrict__ act,
              int M, int Kp) {
    constexpr int NB2 = NP / 8;
    constexpr int NB4 = NP / 16;
    constexpr uint32_t ASZ = 128 * 72 * 2;   // bytes per A stage
    constexpr uint32_t BSZ = NP * 72 * 2;    // bytes per B stage
    extern __shared__ char dyn[];
    uint32_t as_base = smem_u32(dyn);                 // 2 stages A
    uint32_t bs_base = as_base + 2 * ASZ;             // 2 stages B

    int tid = threadIdx.x;
    int w = tid >> 5, l = tid & 31;
    int gm0 = blockIdx.x * 128;
    int lr = l & 7, grp = l >> 3;

    float acc[NB2][4];
#pragma unroll
    for (int f = 0; f < NB2; f++)
#pragma unroll
        for (int q = 0; q < 4; q++) acc[f][q] = 0.f;

    int a_row = w * 16 + lr + ((grp & 1) ? 8 : 0);
    int a_colofs = (grp & 2) ? 8 : 0;
    int b_rowofs = lr + ((grp >= 2) ? 8 : 0);
    int b_colofs = (grp & 1) ? 8 : 0;

    const int nc = Kp >> 6;

    // ---- async issue of one chunk into stage st ----
    auto issue = [&](int ci_, int st) {
        int k0 = ci_ << 6;
        uint32_t ab = as_base + st * ASZ;
        uint32_t bb = bs_base + st * BSZ;
#pragma unroll
        for (int it = 0; it < 4; it++) {
            int f = tid + it * 256;
            int row = f >> 3, seg = f & 7;
            int gm = gm0 + row;
            const __half* src = A + (size_t)gm * Kp + k0 + seg * 8;
            uint32_t dst = ab + (row * 72 + seg * 8) * 2;
            CP_A16(dst, src, (gm < M) ? 16 : 0);
        }
        for (int q = tid; q < NP * 8; q += 256) {
            int row = q >> 3, seg = q & 7;
            const __half* src = B + (size_t)row * Kp + k0 + seg * 8;
            uint32_t dst = bb + (row * 72 + seg * 8) * 2;
            CP_A16(dst, src, 16);
        }
        CP_COMMIT();
    };

    issue(0, 0);
    for (int i = 0; i < nc; i++) {
        if (i + 1 < nc) { issue(i + 1, (i + 1) & 1); CP_WAIT1(); }
        else            { CP_WAIT0(); }
        __syncthreads();
        int st = i & 1;
        uint32_t ab = as_base + st * ASZ;
        uint32_t bb = bs_base + st * BSZ;
#pragma unroll
        for (int kb = 0; kb < 64; kb += 16) {
            uint32_t a0, a1, a2, a3;
            {
                uint32_t addr = ab + (a_row * 72 + kb + a_colofs) * 2;
                asm volatile("ldmatrix.sync.aligned.m8n8.x4.shared.b16 {%0,%1,%2,%3}, [%4];"
                             : "=r"(a0), "=r"(a1), "=r"(a2), "=r"(a3) : "r"(addr));
            }
#pragma unroll
            for (int j4 = 0; j4 < NB4; j4++) {
                uint32_t b0, b1, b2, b3;
                uint32_t addr = bb + ((j4 * 16 + b_rowofs) * 72 + kb + b_colofs) * 2;
                asm volatile("ldmatrix.sync.aligned.m8n8.x4.shared.b16 {%0,%1,%2,%3}, [%4];"
                             : "=r"(b0), "=r"(b1), "=r"(b2), "=r"(b3) : "r"(addr));
                asm volatile("mma.sync.aligned.m16n8k16.row.col.f32.f16.f16.f32 "
                             "{%0,%1,%2,%3}, {%4,%5,%6,%7}, {%8,%9}, {%0,%1,%2,%3};"
                             : "+f"(acc[2 * j4][0]), "+f"(acc[2 * j4][1]),
                               "+f"(acc[2 * j4][2]), "+f"(acc[2 * j4][3])
                             : "r"(a0), "r"(a1), "r"(a2), "r"(a3), "r"(b0), "r"(b1));
                asm volatile("mma.sync.aligned.m16n8k16.row.col.f32.f16.f16.f32 "
                             "{%0,%1,%2,%3}, {%4,%5,%6,%7}, {%8,%9}, {%0,%1,%2,%3};"
                             : "+f"(acc[2 * j4 + 1][0]), "+f"(acc[2 * j4 + 1][1]),
                               "+f"(acc[2 * j4 + 1][2]), "+f"(acc[2 * j4 + 1][3])
                             : "r"(a0), "r"(a1), "r"(a2), "r"(a3), "r"(b2), "r"(b3));
            }
        }
        __syncthreads();
    }

    // ---- epilogue ----
    int r = l >> 2, cg = l & 3;
    int row0 = gm0 + w * 16 + r;
    int row1 = row0 + 8;
#pragma unroll
    for (int f = 0; f < NB2; f++) {
        int c = f * 8 + 2 * cg;
        if (c < CO) {
            if (row0 < M) {
                float v0 = acc[f][0] + obias[c];
                act[(size_t)row0 * CO + c] = leaky(v0, 0.01f);
                if (c + 1 < CO) {
                    float v1 = acc[f][1] + obias[c + 1];
                    act[(size_t)row0 * CO + c + 1] = leaky(v1, 0.01f);
                }
            }
            if (row1 < M) {
                float v2 = acc[f][2] + obias[c];
                act[(size_t)row1 * CO + c] = leaky(v2, 0.01f);
                if (c + 1 < CO) {
                    float v3 = acc[f][3] + obias[c + 1];
                    act[(size_t)row1 * CO + c + 1] = leaky(v3, 0.01f);
                }
            }
        }
    }
}

// ================= pooling + head =================
__global__ void pool_k(const float* __restrict__ act, const int* __restrict__ batch,
                       float* pool, float* cnt) {
    int nn = blockIdx.x * blockDim.x + threadIdx.x;
    if (nn >= NNODES) return;
    int gi = batch[nn];
    atomicAdd(&cnt[gi], 1.0f);
#pragma unroll
    for (int c = 0; c < 5; c++) atomicAdd(&pool[gi * 5 + c], act[nn * 5 + c]);
}

__global__ void head_k(const float* __restrict__ pool, const float* __restrict__ cnt,
                       const float* __restrict__ cond, const float* __restrict__ fcW,
                       const float* __restrict__ fcb, float* out) {
    int gi = blockIdx.x * blockDim.x + threadIdx.x;
    if (gi >= NGRAPH) return;
    float cd = 0.f;
    for (int k = 0; k < NCOND; k++) cd += cond[k] * fcW[5 + k];
    float c = fmaxf(cnt[gi], 1.0f);
    float acc = fcb[0] + cd;
#pragma unroll
    for (int j = 0; j < 5; j++) acc += (pool[gi * 5 + j] / c) * fcW[j];
    out[gi] = 1.0f / (1.0f + expf(-acc));
}

// ================= host orchestration =================
extern "C" void kernel_launch(void* const* d_in, const int* in_sizes, int n_in,
                              void* d_out, int out_size) {
    (void)in_sizes; (void)n_in; (void)out_size;
    const float* x     = (const float*)d_in[0];
    const int*   ei    = (const int*)d_in[1];
    const int*   batch = (const int*)d_in[2];
    const float* cond  = (const float*)d_in[3];
    const float* W[4]  = {(const float*)d_in[4],  (const float*)d_in[8],
                          (const float*)d_in[12], (const float*)d_in[16]};
    const float* As_[4] = {(const float*)d_in[5],  (const float*)d_in[9],
                           (const float*)d_in[13], (const float*)d_in[17]};
    const float* Ad_[4] = {(const float*)d_in[6],  (const float*)d_in[10],
                           (const float*)d_in[14], (const float*)d_in[18]};
    const float* Bb[4] = {(const float*)d_in[7],  (const float*)d_in[11],
                          (const float*)d_in[15], (const float*)d_in[19]};
    const float* G[4]  = {(const float*)d_in[20], (const float*)d_in[22],
                          (const float*)d_in[24], (const float*)d_in[26]};
    const float* Be[4] = {(const float*)d_in[21], (const float*)d_in[23],
                          (const float*)d_in[25], (const float*)d_in[27]};
    const float* fcW = (const float*)d_in[30];
    const float* fcb = (const float*)d_in[31];
    float* outp = (float*)d_out;

    float *p_Y, *p_act, *p_S, *p_U, *p_P, *p_cbias, *p_V, *p_obias;
    float *p_bnsum, *p_scale, *p_shift, *p_pool, *p_cnt;
    int *p_deg, *p_cursor, *p_rowstart, *p_csrc;
    cudaGetSymbolAddress((void**)&p_Y, g_Y);
    cudaGetSymbolAddress((void**)&p_act, g_act);
    cudaGetSymbolAddress((void**)&p_S, g_S);
    cudaGetSymbolAddress((void**)&p_U, g_U);
    cudaGetSymbolAddress((void**)&p_P, g_P);
    cudaGetSymbolAddress((void**)&p_cbias, g_cbias);
    cudaGetSymbolAddress((void**)&p_V, g_V);
    cudaGetSymbolAddress((void**)&p_obias, g_obias);
    cudaGetSymbolAddress((void**)&p_bnsum, g_bnsum);
    cudaGetSymbolAddress((void**)&p_scale, g_scale);
    cudaGetSymbolAddress((void**)&p_shift, g_shift);
    cudaGetSymbolAddress((void**)&p_pool, g_pool);
    cudaGetSymbolAddress((void**)&p_cnt, g_cnt);
    cudaGetSymbolAddress((void**)&p_deg, g_deg);
    cudaGetSymbolAddress((void**)&p_cursor, g_cursor);
    cudaGetSymbolAddress((void**)&p_rowstart, g_rowstart);
    cudaGetSymbolAddress((void**)&p_csrc, g_csrc);

    __half* Yh = (__half*)p_Y;
    __half* Vt = (__half*)p_V;

    const int ci_arr[4] = {128, 90, 45, 15};
    const int co_arr[4] = {90, 45, 15, 5};
    const int np_arr[4] = {96, 48, 16, 16};
    const int kp_arr[4] = {4096, 2880, 1472, 512};
    const int N = NNODES;

    // dynamic smem opt-in
    const int smem1 = 2 * 128 * 72 * 2 + 2 * 96 * 72 * 2;
    const int smem2 = 2 * 128 * 72 * 2 + 2 * 48 * 72 * 2;
    const int smem3 = 2 * 128 * 72 * 2 + 2 * 16 * 72 * 2;
    cudaFuncSetAttribute(proj_mma<96, 90>, cudaFuncAttributeMaxDynamicSharedMemorySize, smem1);
    cudaFuncSetAttribute(proj_mma<48, 45>, cudaFuncAttributeMaxDynamicSharedMemorySize, smem2);
    cudaFuncSetAttribute(proj_mma<16, 15>, cudaFuncAttributeMaxDynamicSharedMemorySize, smem3);
    cudaFuncSetAttribute(proj_mma<16, 5>,  cudaFuncAttributeMaxDynamicSharedMemorySize, smem3);

    // ---- CSR by dst ----
    cudaMemsetAsync(p_deg, 0, 40960 * sizeof(int), 0);
    deg_k<<<(ETOT + 255) / 256, 256>>>(ei, p_deg);
    scan_deg<<<1, 1024>>>(p_deg, p_rowstart);
    cudaMemcpyAsync(p_cursor, p_rowstart, NNODES * sizeof(int),
                    cudaMemcpyDeviceToDevice, 0);
    scatter_k<<<(ETOT + 255) / 256, 256>>>(ei, p_cursor, p_csrc);

    const float* X = x;
    for (int l = 0; l < 4; l++) {
        int ci = ci_arr[l], co = co_arr[l], hco = NHEADS * co;
        int K = 32 * ci, Kp = kp_arr[l], NP = np_arr[l];

        // BN fold
        cudaMemsetAsync(p_bnsum, 0, 2 * ci * sizeof(float), 0);
        {
            int bdim = ((ci + 31) / 32) * 32;
            bn_accum<<<(N + 255) / 256, bdim>>>(X, N, ci, p_bnsum);
        }
        bn_final<<<1, 128>>>(p_bnsum, G[l], Be[l], p_scale, p_shift, N, ci);

        // parameter prep
        p_build<<<(ci * 64 + 255) / 256, 256>>>(W[l], As_[l], Ad_[l], p_scale, p_U, p_P, ci, co, hco);
        cbias_k<<<1, 64>>>(p_U, p_shift, p_cbias, ci);
        vt_build<<<(NP * Kp + 255) / 256, 256>>>(W[l], p_scale, Vt, ci, co, hco, NP, K, Kp);
        obias_k<<<co, 256>>>(W[l], p_shift, Bb[l], p_obias, ci, co, hco);

        // attention scores
        score_k<<<(N * 16 + 255) / 256, 256>>>(X, p_P, p_cbias, p_S, N, ci);

        // fused softmax + aggregation into fp16 Y [N, Kp]
        switch (l) {
            case 0: agg_k<128><<<N, 128>>>(p_rowstart, p_csrc, p_S, X, Yh, Kp); break;
            case 1: agg_k<90><<<N, 128>>>(p_rowstart, p_csrc, p_S, X, Yh, Kp); break;
            case 2: agg_k<45><<<N, 128>>>(p_rowstart, p_csrc, p_S, X, Yh, Kp); break;
            case 3: agg_k<15><<<N, 128>>>(p_rowstart, p_csrc, p_S, X, Yh, Kp); break;
        }

        // HMMA projection GEMM with leaky epilogue
        int gblocks = (N + 127) / 128;
        switch (l) {
            case 0: proj_mma<96, 90><<<gblocks, 256, smem1>>>(Yh, Vt, p_obias, p_act, N, Kp); break;
            case 1: proj_mma<48, 45><<<gblocks, 256, smem2>>>(Yh, Vt, p_obias, p_act, N, Kp); break;
            case 2: proj_mma<16, 15><<<gblocks, 256, smem3>>>(Yh, Vt, p_obias, p_act, N, Kp); break;
            case 3: proj_mma<16, 5><<<gblocks, 256, smem3>>>(Yh, Vt, p_obias, p_act, N, Kp); break;
        }
        X = p_act;
    }

    // pooling + head
    cudaMemsetAsync(p_pool, 0, NGRAPH * 5 * sizeof(float), 0);
    cudaMemsetAsync(p_cnt, 0, NGRAPH * sizeof(float), 0);
    pool_k<<<(NNODES + 255) / 256, 256>>>(p_act, batch, p_pool, p_cnt);
    head_k<<<1, 256>>>(p_pool, p_cnt, cond, fcW, fcb, outp);
}